// round 8
// baseline (speedup 1.0000x reference)
#include <cuda_runtime.h>
#include <stdint.h>

// reference(x) = (U*S)@Vh from SVD of x == exact SVD reconstruction == x.
// Kernel = pure D2D streaming copy of N*3*3 floats (75.5 MB R+W).
//
// Final form (champion R2 config): float4 loads, 8 independent per thread
// (MLP=8, 128B/thread), block-strided, exact-fit single-wave grid, 32-bit
// indexing. Measured at ~6.9 TB/s combined = 86% of HBM spec; L2-residency
// (R3/R7), 256-bit ops (R5/R7) and driver memcpy (R4) all tested and did
// not beat this — this is the HBM R+W floor for an identity copy.

#define CP_THREADS 256
#define CP_UNROLL  8

__global__ void __launch_bounds__(CP_THREADS) copy_unroll_kernel(
    const float4* __restrict__ src, float4* __restrict__ dst, int n4)
{
    int base = blockIdx.x * (CP_THREADS * CP_UNROLL) + threadIdx.x;

    if (base + (CP_UNROLL - 1) * CP_THREADS < n4) {
        float4 v[CP_UNROLL];
#pragma unroll
        for (int u = 0; u < CP_UNROLL; u++)
            v[u] = src[base + u * CP_THREADS];
#pragma unroll
        for (int u = 0; u < CP_UNROLL; u++)
            dst[base + u * CP_THREADS] = v[u];
    } else {
#pragma unroll
        for (int u = 0; u < CP_UNROLL; u++) {
            int i = base + u * CP_THREADS;
            if (i < n4) dst[i] = src[i];
        }
    }
}

__global__ void __launch_bounds__(256) copy_f_tail_kernel(
    const float* __restrict__ src, float* __restrict__ dst,
    long long start, long long n)
{
    long long i = start + (long long)blockIdx.x * blockDim.x + threadIdx.x;
    if (i < n) dst[i] = src[i];
}

extern "C" void kernel_launch(void* const* d_in, const int* in_sizes, int n_in,
                              void* d_out, int out_size) {
    const float* x = (const float*)d_in[0];
    float* out = (float*)d_out;
    long long n = (long long)in_sizes[0];   // total float elements (N*3*3)

    long long n4ll = n / 4;
    if (n4ll > 0) {
        int n4 = (int)n4ll;                 // 2,359,296 << 2^31
        long long per_block = (long long)CP_THREADS * CP_UNROLL;
        int blocks = (int)((n4ll + per_block - 1) / per_block);
        copy_unroll_kernel<<<blocks, CP_THREADS>>>((const float4*)x, (float4*)out, n4);
    }
    long long tail_start = n4ll * 4;
    if (n - tail_start > 0) {
        copy_f_tail_kernel<<<1, 256>>>(x, out, tail_start, n);
    }
}